// round 11
// baseline (speedup 1.0000x reference)
#include <cuda_runtime.h>
#include <cuda_bf16.h>
#include <math.h>
#include <stdint.h>

// Problem constants
#define NV 50000
#define NE 640000
#define NHALF 320000
#define TILE_E 64
#define HALF_TILES (NHALF/TILE_E)   // 5000
#define GRID_HALF 148
#define R2 474
#define FIN 128
#define FOUT 128
#define CSTR 132                    // node-kernel padded fp32 stride

// edge-kernel smem layout (bytes); bf16 row stride 272B (17x16B -> LDSM conflict-free)
#define QSTRB 272
#define SM_QHI   0
#define SM_QLO   34816              // 128*272
#define SM_AHI   69632
#define SM_ALO   87040              // + 64*272
#define SM_SCALE 104448             // 256 floats
#define SM_DST   105472             // 64 ints
#define EDGE_SMEM 105728

// ---------------- scratch ----------------------------------------------------
__device__ float g_hacc[(size_t)NV * FOUT];
__device__ float g_h2[(size_t)NV * FOUT];
__device__ __align__(16) float g_Qin[FIN * FOUT];
__device__ __align__(16) float g_Qout[FIN * FOUT];
__device__ __align__(16) float g_w1a[FIN * 4];
__device__ __align__(16) float g_w2a[FIN * 4];
__device__ float g_sum[FOUT];
__device__ float g_sumsq[FOUT];

// ---------------- helpers -----------------------------------------------------
__device__ __forceinline__ uint32_t smem_u32(const void* p) {
    uint32_t a;
    asm("{ .reg .u64 t; cvta.to.shared.u64 t, %1; cvt.u32.u64 %0, t; }" : "=r"(a) : "l"(p));
    return a;
}
__device__ __forceinline__ void ldsm_x4(uint32_t& r0, uint32_t& r1, uint32_t& r2,
                                        uint32_t& r3, uint32_t addr) {
    asm volatile("ldmatrix.sync.aligned.m8n8.x4.shared.b16 {%0,%1,%2,%3}, [%4];"
                 : "=r"(r0), "=r"(r1), "=r"(r2), "=r"(r3) : "r"(addr));
}
__device__ __forceinline__ void mma_bf16(float* c, const uint32_t* a,
                                         uint32_t b0, uint32_t b1) {
    asm volatile(
        "mma.sync.aligned.m16n8k16.row.col.f32.bf16.bf16.f32 "
        "{%0,%1,%2,%3}, {%4,%5,%6,%7}, {%8,%9}, {%0,%1,%2,%3};"
        : "+f"(c[0]), "+f"(c[1]), "+f"(c[2]), "+f"(c[3])
        : "r"(a[0]), "r"(a[1]), "r"(a[2]), "r"(a[3]), "r"(b0), "r"(b1));
}

// ---------------- kernel 0: zero scratch -------------------------------------
__global__ void zero_kernel() {
    int idx = blockIdx.x * blockDim.x + threadIdx.x;
    const int n4 = NV * FOUT / 4;
    float4 z = make_float4(0.f, 0.f, 0.f, 0.f);
    for (int i = idx; i < n4; i += gridDim.x * blockDim.x)
        ((float4*)g_hacc)[i] = z;
    if (idx < FOUT) { g_sum[idx] = 0.f; g_sumsq[idx] = 0.f; }
}

// ---------------- kernel 1a: fold attention weights --------------------------
__global__ void wfold_kernel(const float* __restrict__ node_w,
                             const float* __restrict__ node_rel_w,
                             const float* __restrict__ att_w) {
    int i = threadIdx.x;
    if (i >= 128) return;
#pragma unroll
    for (int k = 0; k < 4; k++) {
        float s1 = 0.f, s2 = 0.f;
#pragma unroll
        for (int d = 0; d < 32; d++) {
            s1 = fmaf(node_rel_w[k * 4096 + i * 32 + d], att_w[d], s1);
            s2 = fmaf(node_w[k * 4096 + i * 32 + d], att_w[32 + d], s2);
        }
        g_w1a[i * 4 + k] = s1;
        g_w2a[i * 4 + k] = s2;
    }
}

// ---------------- kernel 1b: fold projection weights -------------------------
__global__ void qfold_kernel(const float* __restrict__ node_rel_w,
                             const float* __restrict__ in_w,
                             const float* __restrict__ out_w) {
    __shared__ float nrw_s[128];
    int i = blockIdx.x;
    int tid = threadIdx.x;
    {
        int k = tid >> 5, d = tid & 31;
        nrw_s[tid] = node_rel_w[k * 4096 + i * 32 + d];
    }
    __syncthreads();
    int k = tid >> 5, o = tid & 31;
    float qi = 0.f, qo = 0.f;
#pragma unroll
    for (int d = 0; d < 32; d++) {
        float w = nrw_s[k * 32 + d];
        qi = fmaf(w, in_w[k * 1024 + d * 32 + o], qi);
        qo = fmaf(w, out_w[k * 1024 + d * 32 + o], qo);
    }
    g_Qin[i * 128 + tid] = qi;
    g_Qout[i * 128 + tid] = qo;
}

// ---------------- kernel 2: edge kernel (mma.sync bf16-split, 32x32 warps) ---
__global__ void __launch_bounds__(256, 2) edge_kernel(
    const float* __restrict__ node_repr, const float* __restrict__ rel_repr,
    const int* __restrict__ src, const int* __restrict__ dst,
    const int* __restrict__ etype, const float* __restrict__ nrm) {
    extern __shared__ __align__(16) char smem[];
    uint32_t sb = smem_u32(smem);
    float* s_scale = (float*)(smem + SM_SCALE);
    int*   s_dst   = (int*)(smem + SM_DST);

    int tid = threadIdx.x;
    int wid = tid >> 5;
    int lane = tid & 31;
    int cta = blockIdx.x;
    int halfsel = (cta >= GRID_HALF) ? 1 : 0;
    int tile0 = cta - halfsel * GRID_HALF;
    const float* Q = halfsel ? g_Qout : g_Qin;

    // ---- stage Q as bf16 hi/lo, layout [n][k], row stride 272B (once) ----
    for (int idx = tid; idx < 16384; idx += 256) {
        int n = idx >> 7, k = idx & 127;
        float v = Q[k * 128 + n];
        __nv_bfloat16 hi = __float2bfloat16(v);
        __nv_bfloat16 lo = __float2bfloat16(v - __bfloat162float(hi));
        *(__nv_bfloat16*)(smem + SM_QHI + n * QSTRB + k * 2) = hi;
        *(__nv_bfloat16*)(smem + SM_QLO + n * QSTRB + k * 2) = lo;
    }

    // gather mapping: 4 threads per edge, 8-float interleaved slices:
    // thread l4 covers float cols {8*l4 + 32*q + j}, q=0..3, j=0..7.
    // Lane quad at step q loads a CONTIGUOUS 128B line per row.
    int e    = tid >> 2;
    int l4   = tid & 3;

    // warp tiling: 2 row-bands (32 edges) x 4 col-bands (32 cols)
    int rb = wid & 1, cb = wid >> 1;
    int eb = rb * 32;
    int nb0 = cb * 32;       // whole band inside one k-factor: kfac = cb

    // ldmatrix lane addressing (same lane formulas as validated round-9/10)
    int arin = lane & 7;
    uint32_t a_rowl = (uint32_t)(((lane >> 3) & 1) * 8 + arin);
    uint32_t a_coff = (uint32_t)((lane >> 4) * 16);
    uint32_t b_row  = (uint32_t)((lane >> 4) * 8 + arin);
    uint32_t b_coff = (uint32_t)(((lane >> 3) & 1) * 16);

    for (int t = tile0; t < HALF_TILES; t += GRID_HALF) {
        __syncthreads();   // prior tile fully consumed (GEMM + scatter done)
        int e0 = (t + halfsel * HALF_TILES) * TILE_E;

        // ---- gather + compose + logits; store comp bf16 hi/lo (16B STS) ----
        {
            int isrc = __ldg(src + e0 + e);
            int idst = __ldg(dst + e0 + e);
            int iet  = __ldg(etype + e0 + e);
            float nv = __ldg(nrm + e0 + e);
            if (l4 == 0) s_dst[e] = idst;

            const float4* xs = (const float4*)(node_repr + (size_t)isrc * 128) + l4 * 2;
            const float4* rr = (const float4*)(rel_repr  + (size_t)iet  * 128) + l4 * 2;
            const float4* xd = (const float4*)(node_repr + (size_t)idst * 128) + l4 * 2;
            const float4* w1 = ((const float4*)g_w1a) + l4 * 8;
            const float4* w2 = ((const float4*)g_w2a) + l4 * 8;
            float lg0 = 0.f, lg1 = 0.f, lg2 = 0.f, lg3 = 0.f;
#pragma unroll
            for (int q = 0; q < 4; q++) {
                float4 a0 = xs[q * 8], a1 = xs[q * 8 + 1];
                float4 r0 = rr[q * 8], r1 = rr[q * 8 + 1];
                float4 d0 = xd[q * 8], d1 = xd[q * 8 + 1];
                float4 c0, c1;
                c0.x = a0.x * r0.x; c0.y = a0.y * r0.y; c0.z = a0.z * r0.z; c0.w = a0.w * r0.w;
                c1.x = a1.x * r1.x; c1.y = a1.y * r1.y; c1.z = a1.z * r1.z; c1.w = a1.w * r1.w;
                {
                    __nv_bfloat162 h01 = __floats2bfloat162_rn(c0.x, c0.y);
                    __nv_bfloat162 h23 = __floats2bfloat162_rn(c0.z, c0.w);
                    __nv_bfloat162 h45 = __floats2bfloat162_rn(c1.x, c1.y);
                    __nv_bfloat162 h67 = __floats2bfloat162_rn(c1.z, c1.w);
                    __nv_bfloat162 l01 = __floats2bfloat162_rn(
                        c0.x - __bfloat162float(h01.x), c0.y - __bfloat162float(h01.y));
                    __nv_bfloat162 l23 = __floats2bfloat162_rn(
                        c0.z - __bfloat162float(h23.x), c0.w - __bfloat162float(h23.y));
                    __nv_bfloat162 l45 = __floats2bfloat162_rn(
                        c1.x - __bfloat162float(h45.x), c1.y - __bfloat162float(h45.y));
                    __nv_bfloat162 l67 = __floats2bfloat162_rn(
                        c1.z - __bfloat162float(h67.x), c1.w - __bfloat162float(h67.y));
                    uint32_t coff = (uint32_t)(e * QSTRB + (l4 * 8 + q * 32) * 2);
                    uint4 hv, lv;
                    hv.x = *(uint32_t*)&h01; hv.y = *(uint32_t*)&h23;
                    hv.z = *(uint32_t*)&h45; hv.w = *(uint32_t*)&h67;
                    lv.x = *(uint32_t*)&l01; lv.y = *(uint32_t*)&l23;
                    lv.z = *(uint32_t*)&l45; lv.w = *(uint32_t*)&l67;
                    *(uint4*)(smem + SM_AHI + coff) = hv;
                    *(uint4*)(smem + SM_ALO + coff) = lv;
                }
                int ib = q * 32;   // float4-row index of feature base 32*q (+8*l4 in base ptr)
                float4 wv;
                wv = w1[ib + 0]; lg0 = fmaf(c0.x, wv.x, lg0); lg1 = fmaf(c0.x, wv.y, lg1); lg2 = fmaf(c0.x, wv.z, lg2); lg3 = fmaf(c0.x, wv.w, lg3);
                wv = w1[ib + 1]; lg0 = fmaf(c0.y, wv.x, lg0); lg1 = fmaf(c0.y, wv.y, lg1); lg2 = fmaf(c0.y, wv.z, lg2); lg3 = fmaf(c0.y, wv.w, lg3);
                wv = w1[ib + 2]; lg0 = fmaf(c0.z, wv.x, lg0); lg1 = fmaf(c0.z, wv.y, lg1); lg2 = fmaf(c0.z, wv.z, lg2); lg3 = fmaf(c0.z, wv.w, lg3);
                wv = w1[ib + 3]; lg0 = fmaf(c0.w, wv.x, lg0); lg1 = fmaf(c0.w, wv.y, lg1); lg2 = fmaf(c0.w, wv.z, lg2); lg3 = fmaf(c0.w, wv.w, lg3);
                wv = w1[ib + 4]; lg0 = fmaf(c1.x, wv.x, lg0); lg1 = fmaf(c1.x, wv.y, lg1); lg2 = fmaf(c1.x, wv.z, lg2); lg3 = fmaf(c1.x, wv.w, lg3);
                wv = w1[ib + 5]; lg0 = fmaf(c1.y, wv.x, lg0); lg1 = fmaf(c1.y, wv.y, lg1); lg2 = fmaf(c1.y, wv.z, lg2); lg3 = fmaf(c1.y, wv.w, lg3);
                wv = w1[ib + 6]; lg0 = fmaf(c1.z, wv.x, lg0); lg1 = fmaf(c1.z, wv.y, lg1); lg2 = fmaf(c1.z, wv.z, lg2); lg3 = fmaf(c1.z, wv.w, lg3);
                wv = w1[ib + 7]; lg0 = fmaf(c1.w, wv.x, lg0); lg1 = fmaf(c1.w, wv.y, lg1); lg2 = fmaf(c1.w, wv.z, lg2); lg3 = fmaf(c1.w, wv.w, lg3);
                wv = w2[ib + 0]; lg0 = fmaf(d0.x, wv.x, lg0); lg1 = fmaf(d0.x, wv.y, lg1); lg2 = fmaf(d0.x, wv.z, lg2); lg3 = fmaf(d0.x, wv.w, lg3);
                wv = w2[ib + 1]; lg0 = fmaf(d0.y, wv.x, lg0); lg1 = fmaf(d0.y, wv.y, lg1); lg2 = fmaf(d0.y, wv.z, lg2); lg3 = fmaf(d0.y, wv.w, lg3);
                wv = w2[ib + 2]; lg0 = fmaf(d0.z, wv.x, lg0); lg1 = fmaf(d0.z, wv.y, lg1); lg2 = fmaf(d0.z, wv.z, lg2); lg3 = fmaf(d0.z, wv.w, lg3);
                wv = w2[ib + 3]; lg0 = fmaf(d0.w, wv.x, lg0); lg1 = fmaf(d0.w, wv.y, lg1); lg2 = fmaf(d0.w, wv.z, lg2); lg3 = fmaf(d0.w, wv.w, lg3);
                wv = w2[ib + 4]; lg0 = fmaf(d1.x, wv.x, lg0); lg1 = fmaf(d1.x, wv.y, lg1); lg2 = fmaf(d1.x, wv.z, lg2); lg3 = fmaf(d1.x, wv.w, lg3);
                wv = w2[ib + 5]; lg0 = fmaf(d1.y, wv.x, lg0); lg1 = fmaf(d1.y, wv.y, lg1); lg2 = fmaf(d1.y, wv.z, lg2); lg3 = fmaf(d1.y, wv.w, lg3);
                wv = w2[ib + 6]; lg0 = fmaf(d1.z, wv.x, lg0); lg1 = fmaf(d1.z, wv.y, lg1); lg2 = fmaf(d1.z, wv.z, lg2); lg3 = fmaf(d1.z, wv.w, lg3);
                wv = w2[ib + 7]; lg0 = fmaf(d1.w, wv.x, lg0); lg1 = fmaf(d1.w, wv.y, lg1); lg2 = fmaf(d1.w, wv.z, lg2); lg3 = fmaf(d1.w, wv.w, lg3);
            }
            lg0 += __shfl_xor_sync(0xFFFFFFFFu, lg0, 1);
            lg1 += __shfl_xor_sync(0xFFFFFFFFu, lg1, 1);
            lg2 += __shfl_xor_sync(0xFFFFFFFFu, lg2, 1);
            lg3 += __shfl_xor_sync(0xFFFFFFFFu, lg3, 1);
            lg0 += __shfl_xor_sync(0xFFFFFFFFu, lg0, 2);
            lg1 += __shfl_xor_sync(0xFFFFFFFFu, lg1, 2);
            lg2 += __shfl_xor_sync(0xFFFFFFFFu, lg2, 2);
            lg3 += __shfl_xor_sync(0xFFFFFFFFu, lg3, 2);
            if (l4 == 0) {
                float l0 = fmaxf(lg0, 0.f);
                float l1 = fmaxf(lg1, 0.f);
                float l2 = fmaxf(lg2, 0.f);
                float l3 = fmaxf(lg3, 0.f);
                float e0x = expf(l0), e1x = expf(l1), e2x = expf(l2), e3x = expf(l3);
                float inv = nv / (e0x + e1x + e2x + e3x);   // /3 applied in node kernel
                s_scale[e * 4 + 0] = e0x * inv;
                s_scale[e * 4 + 1] = e1x * inv;
                s_scale[e * 4 + 2] = e2x * inv;
                s_scale[e * 4 + 3] = e3x * inv;
            }
        }
        __syncthreads();

        // ---- GEMM: 32 edges x 32 cols per warp, K=128, 3 bf16-split passes ----
        float c[2][4][4];
#pragma unroll
        for (int mf = 0; mf < 2; mf++)
#pragma unroll
            for (int nt = 0; nt < 4; nt++)
#pragma unroll
                for (int j = 0; j < 4; j++) c[mf][nt][j] = 0.f;

#pragma unroll 1
        for (int k = 0; k < 8; k++) {
            // B fragments for this k: 2 n16-bands x (hi, lo)
            uint32_t bh[2][4], bl[2][4];
#pragma unroll
            for (int nf = 0; nf < 2; nf++) {
                uint32_t boff = (uint32_t)(nb0 + nf * 16 + b_row) * QSTRB + b_coff + k * 32;
                ldsm_x4(bh[nf][0], bh[nf][1], bh[nf][2], bh[nf][3], sb + SM_QHI + boff);
                ldsm_x4(bl[nf][0], bl[nf][1], bl[nf][2], bl[nf][3], sb + SM_QLO + boff);
            }
#pragma unroll
            for (int mf = 0; mf < 2; mf++) {
                uint32_t aoff = (uint32_t)(eb + mf * 16 + a_rowl) * QSTRB + a_coff + k * 32;
                uint32_t ahi[4], alo[4];
                ldsm_x4(ahi[0], ahi[1], ahi[2], ahi[3], sb + SM_AHI + aoff);
                ldsm_x4(alo[0], alo[1], alo[2], alo[3], sb + SM_ALO + aoff);
#pragma unroll
                for (int nf = 0; nf < 2; nf++) {
                    mma_bf16(c[mf][2 * nf],     ahi, bh[nf][0], bh[nf][1]);
                    mma_bf16(c[mf][2 * nf],     ahi, bl[nf][0], bl[nf][1]);
                    mma_bf16(c[mf][2 * nf],     alo, bh[nf][0], bh[nf][1]);
                    mma_bf16(c[mf][2 * nf + 1], ahi, bh[nf][2], bh[nf][3]);
                    mma_bf16(c[mf][2 * nf + 1], ahi, bl[nf][2], bl[nf][3]);
                    mma_bf16(c[mf][2 * nf + 1], alo, bh[nf][2], bh[nf][3]);
                }
            }
        }

        // ---- scale + scatter (red.v2); whole band shares k-factor cb ----
#pragma unroll
        for (int mf = 0; mf < 2; mf++) {
            int er0 = eb + mf * 16 + (lane >> 2);
            int er1 = er0 + 8;
            float s0 = s_scale[er0 * 4 + cb];
            float s1 = s_scale[er1 * 4 + cb];
            float* hp0 = g_hacc + (size_t)s_dst[er0] * 128;
            float* hp1 = g_hacc + (size_t)s_dst[er1] * 128;
            int nc0 = nb0 + (lane & 3) * 2;
#pragma unroll
            for (int nt = 0; nt < 4; nt++) {
                int n = nc0 + nt * 8;
                asm volatile("red.global.add.v2.f32 [%0], {%1, %2};"
                    :: "l"(hp0 + n), "f"(c[mf][nt][0] * s0), "f"(c[mf][nt][1] * s0) : "memory");
                asm volatile("red.global.add.v2.f32 [%0], {%1, %2};"
                    :: "l"(hp1 + n), "f"(c[mf][nt][2] * s1), "f"(c[mf][nt][3] * s1) : "memory");
            }
        }
    }
}

// ---------------- kernel 3: node kernel (self-loop GEMM + fused BN stats) ---
__global__ void __launch_bounds__(128) node_kernel(
    const float* __restrict__ loop_rel, const float* __restrict__ loop_w,
    const float* __restrict__ bias) {
    extern __shared__ float sm[];
    float* Ws     = sm;                 // 16384
    float* t      = Ws + 16384;         // 64*CSTR
    float* sh     = t + 64 * CSTR;      // 64*CSTR
    float* colsum = sh + 64 * CSTR;     // 128
    float* colsq  = colsum + 128;       // 128

    int tid = threadIdx.x;
    int row0 = blockIdx.x * 64;

    {
        const float4* Wg = (const float4*)loop_w;
        float4* Ws4 = (float4*)Ws;
#pragma unroll
        for (int q = 0; q < 32; q++) Ws4[tid + q * 128] = Wg[tid + q * 128];
    }
    if (tid < 128) { colsum[tid] = 0.f; colsq[tid] = 0.f; }

    {
        int e = tid >> 1;
        int ioff = (tid & 1) * 64;
        int row = row0 + e;
        float* tp = t + e * CSTR + ioff;
        float* hp = sh + e * CSTR + ioff;
        if (row < NV) {
            const float4* hv4 = (const float4*)(g_hacc + (size_t)row * 128 + ioff);
            const float4* lr4 = (const float4*)(loop_rel + ioff);
#pragma unroll
            for (int q = 0; q < 16; q++) {
                float4 hh = hv4[q];
                hh.x *= (1.f / 3.f); hh.y *= (1.f / 3.f); hh.z *= (1.f / 3.f); hh.w *= (1.f / 3.f);
                *(float4*)(hp + q * 4) = hh;
                float4 lr = lr4[q];
                float4 tv;
                tv.x = hh.x * lr.x; tv.y = hh.y * lr.y; tv.z = hh.z * lr.z; tv.w = hh.w * lr.w;
                *(float4*)(tp + q * 4) = tv;
            }
        } else {
            float4 z = make_float4(0.f, 0.f, 0.f, 0.f);
#pragma unroll
            for (int q = 0; q < 16; q++) {
                *(float4*)(hp + q * 4) = z;
                *(float4*)(tp + q * 4) = z;
            }
        }
    }
    __syncthreads();

    int c4 = tid & 15, r = tid >> 4;
    float acc[8][8];
#pragma unroll
    for (int u = 0; u < 8; u++)
#pragma unroll
        for (int m = 0; m < 8; m++) acc[u][m] = 0.f;

    const float* ap = t + (r * 8) * CSTR;
    const float* bp = Ws + c4 * 4;
#pragma unroll 1
    for (int k = 0; k < 128; k += 4) {
#pragma unroll
        for (int kk = 0; kk < 4; kk++) {
            const float* brow = bp + (k + kk) * 128;
            float bv[8];
#pragma unroll
            for (int m = 0; m < 4; m++) bv[m] = brow[m];
#pragma unroll
            for (int m = 0; m < 4; m++) bv[4 + m] = brow[64 + m];
#pragma unroll
            for (int u = 0; u < 8; u++) {
                float av = ap[u * CSTR + k + kk];
#pragma unroll
                for (int m = 0; m < 8; m++) acc[u][m] = fmaf(av, bv[m], acc[u][m]);
            }
        }
    }

    float psum[8], psq[8];
#pragma unroll
    for (int m = 0; m < 8; m++) { psum[m] = 0.f; psq[m] = 0.f; }
#pragma unroll
    for (int u = 0; u < 8; u++) {
        int e = r * 8 + u;
        int row = row0 + e;
        if (row < NV) {
#pragma unroll
            for (int m = 0; m < 8; m++) {
                int col = (m < 4) ? (c4 * 4 + m) : (64 + c4 * 4 + m - 4);
                float v = sh[e * CSTR + col] + acc[u][m] * (1.f / 3.f) + bias[col];
                g_h2[(size_t)row * 128 + col] = v;
                psum[m] += v;
                psq[m] = fmaf(v, v, psq[m]);
            }
        }
    }
#pragma unroll
    for (int m = 0; m < 8; m++) {
        int col = (m < 4) ? (c4 * 4 + m) : (64 + c4 * 4 + m - 4);
        atomicAdd(&colsum[col], psum[m]);
        atomicAdd(&colsq[col], psq[m]);
    }
    __syncthreads();
    if (tid < 128) {
        atomicAdd(&g_sum[tid], colsum[tid]);
        atomicAdd(&g_sumsq[tid], colsq[tid]);
    }
}

// ---------------- kernel 4: batchnorm + tanh ---------------------------------
__global__ void finalize_kernel(const float* __restrict__ gamma,
                                const float* __restrict__ beta,
                                float* __restrict__ out) {
    __shared__ float sa[128], sb_[128];
    int tid = threadIdx.x;
    if (tid < 128) {
        float mean = g_sum[tid] * (1.f / NV);
        float var = g_sumsq[tid] * (1.f / NV) - mean * mean;
        float a = gamma[tid] * rsqrtf(var + 1e-5f);
        sa[tid] = a;
        sb_[tid] = beta[tid] - mean * a;
    }
    __syncthreads();
    const int n4 = NV * FOUT / 4;
    for (int i = blockIdx.x * blockDim.x + tid; i < n4; i += gridDim.x * blockDim.x) {
        float4 v = ((const float4*)g_h2)[i];
        int c0 = (i * 4) & 127;
        float4 y;
        y.x = tanhf(fmaf(v.x, sa[c0 + 0], sb_[c0 + 0]));
        y.y = tanhf(fmaf(v.y, sa[c0 + 1], sb_[c0 + 1]));
        y.z = tanhf(fmaf(v.z, sa[c0 + 2], sb_[c0 + 2]));
        y.w = tanhf(fmaf(v.w, sa[c0 + 3], sb_[c0 + 3]));
        ((float4*)out)[i] = y;
    }
}

// ---------------- kernel 5: rel_out = rel_repr @ w_rel -----------------------
__global__ void relout_kernel(const float* __restrict__ rel_repr,
                              const float* __restrict__ w_rel,
                              float* __restrict__ out) {
    __shared__ float rrow[128];
    int b = blockIdx.x, tid = threadIdx.x;
    rrow[tid] = rel_repr[b * 128 + tid];
    __syncthreads();
    float s = 0.f;
#pragma unroll 4
    for (int i = 0; i < 128; i++) s = fmaf(rrow[i], w_rel[i * 128 + tid], s);
    out[(size_t)NV * FOUT + b * 128 + tid] = s;
}

// ---------------- host launcher ----------------------------------------------
extern "C" void kernel_launch(void* const* d_in, const int* in_sizes, int n_in,
                              void* d_out, int out_size) {
    const float* node_repr  = (const float*)d_in[0];
    const float* rel_repr   = (const float*)d_in[1];
    const int*   src        = (const int*)d_in[2];
    const int*   dst        = (const int*)d_in[3];
    const int*   etype      = (const int*)d_in[4];
    const float* nrm        = (const float*)d_in[5];
    const float* node_w     = (const float*)d_in[6];
    const float* node_rel_w = (const float*)d_in[7];
    const float* in_w       = (const float*)d_in[8];
    const float* out_w      = (const float*)d_in[9];
    const float* att_w      = (const float*)d_in[10];
    const float* loop_rel   = (const float*)d_in[11];
    const float* loop_w     = (const float*)d_in[12];
    const float* w_rel      = (const float*)d_in[13];
    const float* bias       = (const float*)d_in[14];
    const float* bn_gamma   = (const float*)d_in[15];
    const float* bn_beta    = (const float*)d_in[16];
    float* out = (float*)d_out;

    static const int NODE_SMEM = (16384 + 2 * 64 * CSTR + 256) * 4;
    cudaFuncSetAttribute(edge_kernel, cudaFuncAttributeMaxDynamicSharedMemorySize, EDGE_SMEM);
    cudaFuncSetAttribute(node_kernel, cudaFuncAttributeMaxDynamicSharedMemorySize, NODE_SMEM);

    zero_kernel<<<512, 256>>>();
    wfold_kernel<<<1, 128>>>(node_w, node_rel_w, att_w);
    qfold_kernel<<<128, 128>>>(node_rel_w, in_w, out_w);
    edge_kernel<<<2 * GRID_HALF, 256, EDGE_SMEM>>>(node_repr, rel_repr, src, dst, etype, nrm);
    node_kernel<<<(NV + 63) / 64, 128, NODE_SMEM>>>(loop_rel, loop_w, bias);
    finalize_kernel<<<1024, 256>>>(bn_gamma, bn_beta, out);
    relout_kernel<<<R2, 128>>>(rel_repr, w_rel, out);
}

// round 12
// speedup vs baseline: 1.4240x; 1.4240x over previous
#include <cuda_runtime.h>
#include <cuda_bf16.h>
#include <math.h>
#include <stdint.h>

// Problem constants
#define NV 50000
#define NE 640000
#define NHALF 320000
#define TILE_E 64
#define HALF_TILES (NHALF/TILE_E)   // 5000
#define GRID_HALF 148
#define R2 474
#define FIN 128
#define FOUT 128
#define CSTR 132                    // node-kernel padded fp32 stride

// edge-kernel smem layout (bytes); bf16 row stride 272B (17x16B -> LDSM conflict-free)
#define QSTRB 272
#define SM_QHI   0
#define SM_QLO   34816              // 128*272
#define SM_AHI   69632
#define SM_ALO   87040              // + 64*272
#define SM_SCALE 104448             // 256 floats
#define SM_DST   105472             // 64 ints
#define EDGE_SMEM 105728

// ---------------- scratch ----------------------------------------------------
__device__ float g_hacc[(size_t)NV * FOUT];
__device__ float g_h2[(size_t)NV * FOUT];
__device__ __align__(16) float g_Qin[FIN * FOUT];
__device__ __align__(16) float g_Qout[FIN * FOUT];
__device__ __align__(16) float g_w1a[FIN * 4];
__device__ __align__(16) float g_w2a[FIN * 4];
__device__ __align__(16) float g_ndot[(size_t)NV * 4];   // x_v . w2a[:,k]
__device__ float g_sum[FOUT];
__device__ float g_sumsq[FOUT];

// ---------------- helpers -----------------------------------------------------
__device__ __forceinline__ uint32_t smem_u32(const void* p) {
    uint32_t a;
    asm("{ .reg .u64 t; cvta.to.shared.u64 t, %1; cvt.u32.u64 %0, t; }" : "=r"(a) : "l"(p));
    return a;
}
__device__ __forceinline__ void ldsm_x4(uint32_t& r0, uint32_t& r1, uint32_t& r2,
                                        uint32_t& r3, uint32_t addr) {
    asm volatile("ldmatrix.sync.aligned.m8n8.x4.shared.b16 {%0,%1,%2,%3}, [%4];"
                 : "=r"(r0), "=r"(r1), "=r"(r2), "=r"(r3) : "r"(addr));
}
__device__ __forceinline__ void mma_bf16(float* c, const uint32_t* a,
                                         uint32_t b0, uint32_t b1) {
    asm volatile(
        "mma.sync.aligned.m16n8k16.row.col.f32.bf16.bf16.f32 "
        "{%0,%1,%2,%3}, {%4,%5,%6,%7}, {%8,%9}, {%0,%1,%2,%3};"
        : "+f"(c[0]), "+f"(c[1]), "+f"(c[2]), "+f"(c[3])
        : "r"(a[0]), "r"(a[1]), "r"(a[2]), "r"(a[3]), "r"(b0), "r"(b1));
}

// ---------------- kernel 0: zero scratch -------------------------------------
__global__ void zero_kernel() {
    int idx = blockIdx.x * blockDim.x + threadIdx.x;
    const int n4 = NV * FOUT / 4;
    float4 z = make_float4(0.f, 0.f, 0.f, 0.f);
    for (int i = idx; i < n4; i += gridDim.x * blockDim.x)
        ((float4*)g_hacc)[i] = z;
    if (idx < FOUT) { g_sum[idx] = 0.f; g_sumsq[idx] = 0.f; }
}

// ---------------- kernel 1a: fold attention weights --------------------------
__global__ void wfold_kernel(const float* __restrict__ node_w,
                             const float* __restrict__ node_rel_w,
                             const float* __restrict__ att_w) {
    int i = threadIdx.x;
    if (i >= 128) return;
#pragma unroll
    for (int k = 0; k < 4; k++) {
        float s1 = 0.f, s2 = 0.f;
#pragma unroll
        for (int d = 0; d < 32; d++) {
            s1 = fmaf(node_rel_w[k * 4096 + i * 32 + d], att_w[d], s1);
            s2 = fmaf(node_w[k * 4096 + i * 32 + d], att_w[32 + d], s2);
        }
        g_w1a[i * 4 + k] = s1;
        g_w2a[i * 4 + k] = s2;
    }
}

// ---------------- kernel 1b: fold projection weights -------------------------
__global__ void qfold_kernel(const float* __restrict__ node_rel_w,
                             const float* __restrict__ in_w,
                             const float* __restrict__ out_w) {
    __shared__ float nrw_s[128];
    int i = blockIdx.x;
    int tid = threadIdx.x;
    {
        int k = tid >> 5, d = tid & 31;
        nrw_s[tid] = node_rel_w[k * 4096 + i * 32 + d];
    }
    __syncthreads();
    int k = tid >> 5, o = tid & 31;
    float qi = 0.f, qo = 0.f;
#pragma unroll
    for (int d = 0; d < 32; d++) {
        float w = nrw_s[k * 32 + d];
        qi = fmaf(w, in_w[k * 1024 + d * 32 + o], qi);
        qo = fmaf(w, out_w[k * 1024 + d * 32 + o], qo);
    }
    g_Qin[i * 128 + tid] = qi;
    g_Qout[i * 128 + tid] = qo;
}

// ---------------- kernel 1c: per-node dst attention term ---------------------
// ndot[v][k] = sum_i node_repr[v][i] * w2a[i][k]  (one warp per node)
__global__ void ndot_kernel(const float* __restrict__ node_repr) {
    int warp = (blockIdx.x * blockDim.x + threadIdx.x) >> 5;
    int lane = threadIdx.x & 31;
    if (warp >= NV) return;
    float4 x = ((const float4*)(node_repr + (size_t)warp * 128))[lane];
    const float4* w2 = ((const float4*)g_w2a) + lane * 4;  // rows i = lane*4 + j
    float s0 = 0.f, s1 = 0.f, s2 = 0.f, s3 = 0.f;
    float4 wv;
    wv = w2[0]; s0 = fmaf(x.x, wv.x, s0); s1 = fmaf(x.x, wv.y, s1); s2 = fmaf(x.x, wv.z, s2); s3 = fmaf(x.x, wv.w, s3);
    wv = w2[1]; s0 = fmaf(x.y, wv.x, s0); s1 = fmaf(x.y, wv.y, s1); s2 = fmaf(x.y, wv.z, s2); s3 = fmaf(x.y, wv.w, s3);
    wv = w2[2]; s0 = fmaf(x.z, wv.x, s0); s1 = fmaf(x.z, wv.y, s1); s2 = fmaf(x.z, wv.z, s2); s3 = fmaf(x.z, wv.w, s3);
    wv = w2[3]; s0 = fmaf(x.w, wv.x, s0); s1 = fmaf(x.w, wv.y, s1); s2 = fmaf(x.w, wv.z, s2); s3 = fmaf(x.w, wv.w, s3);
#pragma unroll
    for (int off = 16; off > 0; off >>= 1) {
        s0 += __shfl_xor_sync(0xFFFFFFFFu, s0, off);
        s1 += __shfl_xor_sync(0xFFFFFFFFu, s1, off);
        s2 += __shfl_xor_sync(0xFFFFFFFFu, s2, off);
        s3 += __shfl_xor_sync(0xFFFFFFFFu, s3, off);
    }
    if (lane == 0)
        ((float4*)g_ndot)[warp] = make_float4(s0, s1, s2, s3);
}

// ---------------- kernel 2: edge kernel (round-10 champion + ndot) -----------
// Persistent, grid = 2*GRID_HALF, 256 threads. Per 64-edge tile:
// gather x_src*rel (coalesced interleaved slices) + logits (w1a fold + ndot[dst])
// -> comp bf16 hi/lo -> HMMA 3-pass 16x64-warp GEMM -> red.v2 scatter.
__global__ void __launch_bounds__(256, 2) edge_kernel(
    const float* __restrict__ node_repr, const float* __restrict__ rel_repr,
    const int* __restrict__ src, const int* __restrict__ dst,
    const int* __restrict__ etype, const float* __restrict__ nrm) {
    extern __shared__ __align__(16) char smem[];
    uint32_t sb = smem_u32(smem);
    float* s_scale = (float*)(smem + SM_SCALE);
    int*   s_dst   = (int*)(smem + SM_DST);

    int tid = threadIdx.x;
    int wid = tid >> 5;
    int lane = tid & 31;
    int cta = blockIdx.x;
    int halfsel = (cta >= GRID_HALF) ? 1 : 0;
    int tile0 = cta - halfsel * GRID_HALF;
    const float* Q = halfsel ? g_Qout : g_Qin;

    // ---- stage Q as bf16 hi/lo, layout [n][k], row stride 272B (once) ----
    for (int idx = tid; idx < 16384; idx += 256) {
        int n = idx >> 7, k = idx & 127;
        float v = Q[k * 128 + n];
        __nv_bfloat16 hi = __float2bfloat16(v);
        __nv_bfloat16 lo = __float2bfloat16(v - __bfloat162float(hi));
        *(__nv_bfloat16*)(smem + SM_QHI + n * QSTRB + k * 2) = hi;
        *(__nv_bfloat16*)(smem + SM_QLO + n * QSTRB + k * 2) = lo;
    }

    // gather mapping: 4 threads per edge, interleaved 4-float slices:
    // thread l4 covers float cols {4*l4 + 16*q + j}, q=0..7.
    int e    = tid >> 2;
    int l4   = tid & 3;

    // warp tiling: 4 row-bands x 2 col-halves (16 edges x 64 cols per warp)
    int rb = wid & 3, ch = wid >> 2;
    int eb = rb * 16;

    // ldmatrix lane addressing
    int arin = lane & 7;
    uint32_t a_row  = (uint32_t)(eb + ((lane >> 3) & 1) * 8 + arin);
    uint32_t a_coff = (uint32_t)((lane >> 4) * 16);
    uint32_t ahi_base = sb + SM_AHI + a_row * QSTRB + a_coff;
    uint32_t alo_base = sb + SM_ALO + a_row * QSTRB + a_coff;
    uint32_t b_row  = (uint32_t)((lane >> 4) * 8 + arin);
    uint32_t b_coff = (uint32_t)(((lane >> 3) & 1) * 16);

    for (int t = tile0; t < HALF_TILES; t += GRID_HALF) {
        __syncthreads();   // prior tile fully consumed (GEMM + scatter done)
        int e0 = (t + halfsel * HALF_TILES) * TILE_E;

        // ---- gather + compose + logits; store comp bf16 hi/lo ----
        {
            int isrc = __ldg(src + e0 + e);
            int idst = __ldg(dst + e0 + e);
            int iet  = __ldg(etype + e0 + e);
            float nv = __ldg(nrm + e0 + e);
            if (l4 == 0) s_dst[e] = idst;

            const float4* xs = (const float4*)(node_repr + (size_t)isrc * 128) + l4;
            const float4* rr = (const float4*)(rel_repr  + (size_t)iet  * 128) + l4;
            const float4* w1 = ((const float4*)g_w1a) + l4 * 4;
            float lg0 = 0.f, lg1 = 0.f, lg2 = 0.f, lg3 = 0.f;
#pragma unroll 4
            for (int q = 0; q < 8; q++) {
                float4 a = xs[q * 4], r4 = rr[q * 4];
                float4 c;
                c.x = a.x * r4.x; c.y = a.y * r4.y; c.z = a.z * r4.z; c.w = a.w * r4.w;
                {
                    __nv_bfloat162 h01 = __floats2bfloat162_rn(c.x, c.y);
                    __nv_bfloat162 h23 = __floats2bfloat162_rn(c.z, c.w);
                    __nv_bfloat162 l01 = __floats2bfloat162_rn(
                        c.x - __bfloat162float(h01.x), c.y - __bfloat162float(h01.y));
                    __nv_bfloat162 l23 = __floats2bfloat162_rn(
                        c.z - __bfloat162float(h23.x), c.w - __bfloat162float(h23.y));
                    uint32_t coff = (uint32_t)(e * QSTRB + (l4 * 4 + q * 16) * 2);
                    uint2 hv, lv;
                    hv.x = *(uint32_t*)&h01; hv.y = *(uint32_t*)&h23;
                    lv.x = *(uint32_t*)&l01; lv.y = *(uint32_t*)&l23;
                    *(uint2*)(smem + SM_AHI + coff) = hv;
                    *(uint2*)(smem + SM_ALO + coff) = lv;
                }
                int ib = q * 16;   // w1 float4 row = l4*4 + q*16 + j (l4*4 in base)
                float4 wv;
                wv = w1[ib + 0]; lg0 = fmaf(c.x, wv.x, lg0); lg1 = fmaf(c.x, wv.y, lg1); lg2 = fmaf(c.x, wv.z, lg2); lg3 = fmaf(c.x, wv.w, lg3);
                wv = w1[ib + 1]; lg0 = fmaf(c.y, wv.x, lg0); lg1 = fmaf(c.y, wv.y, lg1); lg2 = fmaf(c.y, wv.z, lg2); lg3 = fmaf(c.y, wv.w, lg3);
                wv = w1[ib + 2]; lg0 = fmaf(c.z, wv.x, lg0); lg1 = fmaf(c.z, wv.y, lg1); lg2 = fmaf(c.z, wv.z, lg2); lg3 = fmaf(c.z, wv.w, lg3);
                wv = w1[ib + 3]; lg0 = fmaf(c.w, wv.x, lg0); lg1 = fmaf(c.w, wv.y, lg1); lg2 = fmaf(c.w, wv.z, lg2); lg3 = fmaf(c.w, wv.w, lg3);
            }
            lg0 += __shfl_xor_sync(0xFFFFFFFFu, lg0, 1);
            lg1 += __shfl_xor_sync(0xFFFFFFFFu, lg1, 1);
            lg2 += __shfl_xor_sync(0xFFFFFFFFu, lg2, 1);
            lg3 += __shfl_xor_sync(0xFFFFFFFFu, lg3, 1);
            lg0 += __shfl_xor_sync(0xFFFFFFFFu, lg0, 2);
            lg1 += __shfl_xor_sync(0xFFFFFFFFu, lg1, 2);
            lg2 += __shfl_xor_sync(0xFFFFFFFFu, lg2, 2);
            lg3 += __shfl_xor_sync(0xFFFFFFFFu, lg3, 2);
            if (l4 == 0) {
                float4 nd = __ldg(((const float4*)g_ndot) + idst);
                float l0 = fmaxf(lg0 + nd.x, 0.f);
                float l1 = fmaxf(lg1 + nd.y, 0.f);
                float l2 = fmaxf(lg2 + nd.z, 0.f);
                float l3 = fmaxf(lg3 + nd.w, 0.f);
                float e0x = expf(l0), e1x = expf(l1), e2x = expf(l2), e3x = expf(l3);
                float inv = nv / (e0x + e1x + e2x + e3x);   // /3 applied in node kernel
                s_scale[e * 4 + 0] = e0x * inv;
                s_scale[e * 4 + 1] = e1x * inv;
                s_scale[e * 4 + 2] = e2x * inv;
                s_scale[e * 4 + 3] = e3x * inv;
            }
        }
        __syncthreads();

        // ---- GEMM: 16 edges x 64 cols per warp, K=128, 3 bf16-split passes ----
        float c[8][4];
#pragma unroll
        for (int nt = 0; nt < 8; nt++)
#pragma unroll
            for (int j = 0; j < 4; j++) c[nt][j] = 0.f;

#pragma unroll 1
        for (int k = 0; k < 8; k++) {
            uint32_t ahi[4], alo[4];
            ldsm_x4(ahi[0], ahi[1], ahi[2], ahi[3], ahi_base + k * 32);
            ldsm_x4(alo[0], alo[1], alo[2], alo[3], alo_base + k * 32);
#pragma unroll
            for (int np = 0; np < 4; np++) {
                int nb = ch * 64 + np * 16;
                uint32_t bh[4], bl[4];
                uint32_t boff = (uint32_t)(nb + b_row) * QSTRB + b_coff + k * 32;
                ldsm_x4(bh[0], bh[1], bh[2], bh[3], sb + SM_QHI + boff);
                ldsm_x4(bl[0], bl[1], bl[2], bl[3], sb + SM_QLO + boff);
                mma_bf16(c[2 * np],     ahi, bh[0], bh[1]);
                mma_bf16(c[2 * np],     ahi, bl[0], bl[1]);
                mma_bf16(c[2 * np],     alo, bh[0], bh[1]);
                mma_bf16(c[2 * np + 1], ahi, bh[2], bh[3]);
                mma_bf16(c[2 * np + 1], ahi, bl[2], bl[3]);
                mma_bf16(c[2 * np + 1], alo, bh[2], bh[3]);
            }
        }

        // ---- scale + scatter straight from fragments (red.v2) ----
        {
            int er0 = eb + (lane >> 2);       // rows for c0,c1
            int er1 = er0 + 8;                // rows for c2,c3
            int nc0 = ch * 64 + (lane & 3) * 2;
            float* hp0 = g_hacc + (size_t)s_dst[er0] * 128;
            float* hp1 = g_hacc + (size_t)s_dst[er1] * 128;
            const float* sp0 = s_scale + er0 * 4;
            const float* sp1 = s_scale + er1 * 4;
#pragma unroll
            for (int nt = 0; nt < 8; nt++) {
                int n = nc0 + nt * 8;
                int kfac = n >> 5;
                float s0 = sp0[kfac], s1 = sp1[kfac];
                asm volatile("red.global.add.v2.f32 [%0], {%1, %2};"
                    :: "l"(hp0 + n), "f"(c[nt][0] * s0), "f"(c[nt][1] * s0) : "memory");
                asm volatile("red.global.add.v2.f32 [%0], {%1, %2};"
                    :: "l"(hp1 + n), "f"(c[nt][2] * s1), "f"(c[nt][3] * s1) : "memory");
            }
        }
    }
}

// ---------------- kernel 3: node kernel (self-loop GEMM + fused BN stats) ---
__global__ void __launch_bounds__(128) node_kernel(
    const float* __restrict__ loop_rel, const float* __restrict__ loop_w,
    const float* __restrict__ bias) {
    extern __shared__ float sm[];
    float* Ws     = sm;                 // 16384
    float* t      = Ws + 16384;         // 64*CSTR
    float* sh     = t + 64 * CSTR;      // 64*CSTR
    float* colsum = sh + 64 * CSTR;     // 128
    float* colsq  = colsum + 128;       // 128

    int tid = threadIdx.x;
    int row0 = blockIdx.x * 64;

    {
        const float4* Wg = (const float4*)loop_w;
        float4* Ws4 = (float4*)Ws;
#pragma unroll
        for (int q = 0; q < 32; q++) Ws4[tid + q * 128] = Wg[tid + q * 128];
    }
    if (tid < 128) { colsum[tid] = 0.f; colsq[tid] = 0.f; }

    {
        int e = tid >> 1;
        int ioff = (tid & 1) * 64;
        int row = row0 + e;
        float* tp = t + e * CSTR + ioff;
        float* hp = sh + e * CSTR + ioff;
        if (row < NV) {
            const float4* hv4 = (const float4*)(g_hacc + (size_t)row * 128 + ioff);
            const float4* lr4 = (const float4*)(loop_rel + ioff);
#pragma unroll
            for (int q = 0; q < 16; q++) {
                float4 hh = hv4[q];
                hh.x *= (1.f / 3.f); hh.y *= (1.f / 3.f); hh.z *= (1.f / 3.f); hh.w *= (1.f / 3.f);
                *(float4*)(hp + q * 4) = hh;
                float4 lr = lr4[q];
                float4 tv;
                tv.x = hh.x * lr.x; tv.y = hh.y * lr.y; tv.z = hh.z * lr.z; tv.w = hh.w * lr.w;
                *(float4*)(tp + q * 4) = tv;
            }
        } else {
            float4 z = make_float4(0.f, 0.f, 0.f, 0.f);
#pragma unroll
            for (int q = 0; q < 16; q++) {
                *(float4*)(hp + q * 4) = z;
                *(float4*)(tp + q * 4) = z;
            }
        }
    }
    __syncthreads();

    int c4 = tid & 15, r = tid >> 4;
    float acc[8][8];
#pragma unroll
    for (int u = 0; u < 8; u++)
#pragma unroll
        for (int m = 0; m < 8; m++) acc[u][m] = 0.f;

    const float* ap = t + (r * 8) * CSTR;
    const float* bp = Ws + c4 * 4;
#pragma unroll 1
    for (int k = 0; k < 128; k += 4) {
#pragma unroll
        for (int kk = 0; kk < 4; kk++) {
            const float* brow = bp + (k + kk) * 128;
            float bv[8];
#pragma unroll
            for (int m = 0; m < 4; m++) bv[m] = brow[m];
#pragma unroll
            for (int m = 0; m < 4; m++) bv[4 + m] = brow[64 + m];
#pragma unroll
            for (int u = 0; u < 8; u++) {
                float av = ap[u * CSTR + k + kk];
#pragma unroll
                for (int m = 0; m < 8; m++) acc[u][m] = fmaf(av, bv[m], acc[u][m]);
            }
        }
    }

    float psum[8], psq[8];
#pragma unroll
    for (int m = 0; m < 8; m++) { psum[m] = 0.f; psq[m] = 0.f; }
#pragma unroll
    for (int u = 0; u < 8; u++) {
        int e = r * 8 + u;
        int row = row0 + e;
        if (row < NV) {
#pragma unroll
            for (int m = 0; m < 8; m++) {
                int col = (m < 4) ? (c4 * 4 + m) : (64 + c4 * 4 + m - 4);
                float v = sh[e * CSTR + col] + acc[u][m] * (1.f / 3.f) + bias[col];
                g_h2[(size_t)row * 128 + col] = v;
                psum[m] += v;
                psq[m] = fmaf(v, v, psq[m]);
            }
        }
    }
#pragma unroll
    for (int m = 0; m < 8; m++) {
        int col = (m < 4) ? (c4 * 4 + m) : (64 + c4 * 4 + m - 4);
        atomicAdd(&colsum[col], psum[m]);
        atomicAdd(&colsq[col], psq[m]);
    }
    __syncthreads();
    if (tid < 128) {
        atomicAdd(&g_sum[tid], colsum[tid]);
        atomicAdd(&g_sumsq[tid], colsq[tid]);
    }
}

// ---------------- kernel 4: batchnorm + tanh ---------------------------------
__global__ void finalize_kernel(const float* __restrict__ gamma,
                                const float* __restrict__ beta,
                                float* __restrict__ out) {
    __shared__ float sa[128], sb_[128];
    int tid = threadIdx.x;
    if (tid < 128) {
        float mean = g_sum[tid] * (1.f / NV);
        float var = g_sumsq[tid] * (1.f / NV) - mean * mean;
        float a = gamma[tid] * rsqrtf(var + 1e-5f);
        sa[tid] = a;
        sb_[tid] = beta[tid] - mean * a;
    }
    __syncthreads();
    const int n4 = NV * FOUT / 4;
    for (int i = blockIdx.x * blockDim.x + tid; i < n4; i += gridDim.x * blockDim.x) {
        float4 v = ((const float4*)g_h2)[i];
        int c0 = (i * 4) & 127;
        float4 y;
        y.x = tanhf(fmaf(v.x, sa[c0 + 0], sb_[c0 + 0]));
        y.y = tanhf(fmaf(v.y, sa[c0 + 1], sb_[c0 + 1]));
        y.z = tanhf(fmaf(v.z, sa[c0 + 2], sb_[c0 + 2]));
        y.w = tanhf(fmaf(v.w, sa[c0 + 3], sb_[c0 + 3]));
        ((float4*)out)[i] = y;
    }
}

// ---------------- kernel 5: rel_out = rel_repr @ w_rel -----------------------
__global__ void relout_kernel(const float* __restrict__ rel_repr,
                              const float* __restrict__ w_rel,
                              float* __restrict__ out) {
    __shared__ float rrow[128];
    int b = blockIdx.x, tid = threadIdx.x;
    rrow[tid] = rel_repr[b * 128 + tid];
    __syncthreads();
    float s = 0.f;
#pragma unroll 4
    for (int i = 0; i < 128; i++) s = fmaf(rrow[i], w_rel[i * 128 + tid], s);
    out[(size_t)NV * FOUT + b * 128 + tid] = s;
}

// ---------------- host launcher ----------------------------------------------
extern "C" void kernel_launch(void* const* d_in, const int* in_sizes, int n_in,
                              void* d_out, int out_size) {
    const float* node_repr  = (const float*)d_in[0];
    const float* rel_repr   = (const float*)d_in[1];
    const int*   src        = (const int*)d_in[2];
    const int*   dst        = (const int*)d_in[3];
    const int*   etype      = (const int*)d_in[4];
    const float* nrm        = (const float*)d_in[5];
    const float* node_w     = (const float*)d_in[6];
    const float* node_rel_w = (const float*)d_in[7];
    const float* in_w       = (const float*)d_in[8];
    const float* out_w      = (const float*)d_in[9];
    const float* att_w      = (const float*)d_in[10];
    const float* loop_rel   = (const float*)d_in[11];
    const float* loop_w     = (const float*)d_in[12];
    const float* w_rel      = (const float*)d_in[13];
    const float* bias       = (const float*)d_in[14];
    const float* bn_gamma   = (const float*)d_in[15];
    const float* bn_beta    = (const float*)d_in[16];
    float* out = (float*)d_out;

    static const int NODE_SMEM = (16384 + 2 * 64 * CSTR + 256) * 4;
    cudaFuncSetAttribute(edge_kernel, cudaFuncAttributeMaxDynamicSharedMemorySize, EDGE_SMEM);
    cudaFuncSetAttribute(node_kernel, cudaFuncAttributeMaxDynamicSharedMemorySize, NODE_SMEM);

    zero_kernel<<<512, 256>>>();
    wfold_kernel<<<1, 128>>>(node_w, node_rel_w, att_w);
    qfold_kernel<<<128, 128>>>(node_rel_w, in_w, out_w);
    ndot_kernel<<<(NV + 7) / 8, 256>>>(node_repr);
    edge_kernel<<<2 * GRID_HALF, 256, EDGE_SMEM>>>(node_repr, rel_repr, src, dst, etype, nrm);
    node_kernel<<<(NV + 63) / 64, 128, NODE_SMEM>>>(loop_rel, loop_w, bias);
    finalize_kernel<<<1024, 256>>>(bn_gamma, bn_beta, out);
    relout_kernel<<<R2, 128>>>(rel_repr, w_rel, out);
}

// round 13
// speedup vs baseline: 1.4852x; 1.0430x over previous
#include <cuda_runtime.h>
#include <cuda_bf16.h>
#include <math.h>
#include <stdint.h>

// Problem constants
#define NV 50000
#define NE 640000
#define NHALF 320000
#define TILE_E 64
#define HALF_TILES (NHALF/TILE_E)   // 5000
#define GRID_HALF 148
#define R2 474
#define FIN 128
#define FOUT 128
#define CSTR 132                    // node-kernel padded fp32 stride

// edge-kernel smem layout (bytes); bf16 row stride 272B (17x16B -> LDSM conflict-free)
#define QSTRB 272
#define SM_QHI   0
#define SM_QLO   34816              // 128*272
#define SM_AHI   69632
#define SM_ALO   87040              // + 64*272
#define SM_SCALE 104448             // 256 floats
#define SM_DST   105472             // 64 ints
#define EDGE_SMEM 105728

// ---------------- scratch ----------------------------------------------------
__device__ float g_hacc[(size_t)NV * FOUT];
__device__ float g_h2[(size_t)NV * FOUT];
__device__ __align__(16) float g_Qin[FIN * FOUT];
__device__ __align__(16) float g_Qout[FIN * FOUT];
__device__ __align__(16) float g_w1a[FIN * 4];
__device__ __align__(16) float g_w2a[FIN * 4];
__device__ __align__(16) float g_ndot[(size_t)NV * 4];   // x_v . w2a[:,k]
__device__ float g_sum[FOUT];
__device__ float g_sumsq[FOUT];

// ---------------- helpers -----------------------------------------------------
__device__ __forceinline__ uint32_t smem_u32(const void* p) {
    uint32_t a;
    asm("{ .reg .u64 t; cvta.to.shared.u64 t, %1; cvt.u32.u64 %0, t; }" : "=r"(a) : "l"(p));
    return a;
}
__device__ __forceinline__ void ldsm_x4(uint32_t& r0, uint32_t& r1, uint32_t& r2,
                                        uint32_t& r3, uint32_t addr) {
    asm volatile("ldmatrix.sync.aligned.m8n8.x4.shared.b16 {%0,%1,%2,%3}, [%4];"
                 : "=r"(r0), "=r"(r1), "=r"(r2), "=r"(r3) : "r"(addr));
}
__device__ __forceinline__ void mma_bf16(float* c, const uint32_t* a,
                                         uint32_t b0, uint32_t b1) {
    asm volatile(
        "mma.sync.aligned.m16n8k16.row.col.f32.bf16.bf16.f32 "
        "{%0,%1,%2,%3}, {%4,%5,%6,%7}, {%8,%9}, {%0,%1,%2,%3};"
        : "+f"(c[0]), "+f"(c[1]), "+f"(c[2]), "+f"(c[3])
        : "r"(a[0]), "r"(a[1]), "r"(a[2]), "r"(a[3]), "r"(b0), "r"(b1));
}

// ---------------- kernel 0: zero scratch -------------------------------------
__global__ void zero_kernel() {
    int idx = blockIdx.x * blockDim.x + threadIdx.x;
    const int n4 = NV * FOUT / 4;
    float4 z = make_float4(0.f, 0.f, 0.f, 0.f);
    for (int i = idx; i < n4; i += gridDim.x * blockDim.x)
        ((float4*)g_hacc)[i] = z;
    if (idx < FOUT) { g_sum[idx] = 0.f; g_sumsq[idx] = 0.f; }
}

// ---------------- kernel 1a: fold attention weights --------------------------
__global__ void wfold_kernel(const float* __restrict__ node_w,
                             const float* __restrict__ node_rel_w,
                             const float* __restrict__ att_w) {
    int i = threadIdx.x;
    if (i >= 128) return;
#pragma unroll
    for (int k = 0; k < 4; k++) {
        float s1 = 0.f, s2 = 0.f;
#pragma unroll
        for (int d = 0; d < 32; d++) {
            s1 = fmaf(node_rel_w[k * 4096 + i * 32 + d], att_w[d], s1);
            s2 = fmaf(node_w[k * 4096 + i * 32 + d], att_w[32 + d], s2);
        }
        g_w1a[i * 4 + k] = s1;
        g_w2a[i * 4 + k] = s2;
    }
}

// ---------------- kernel 1b: fold projection weights -------------------------
__global__ void qfold_kernel(const float* __restrict__ node_rel_w,
                             const float* __restrict__ in_w,
                             const float* __restrict__ out_w) {
    __shared__ float nrw_s[128];
    int i = blockIdx.x;
    int tid = threadIdx.x;
    {
        int k = tid >> 5, d = tid & 31;
        nrw_s[tid] = node_rel_w[k * 4096 + i * 32 + d];
    }
    __syncthreads();
    int k = tid >> 5, o = tid & 31;
    float qi = 0.f, qo = 0.f;
#pragma unroll
    for (int d = 0; d < 32; d++) {
        float w = nrw_s[k * 32 + d];
        qi = fmaf(w, in_w[k * 1024 + d * 32 + o], qi);
        qo = fmaf(w, out_w[k * 1024 + d * 32 + o], qo);
    }
    g_Qin[i * 128 + tid] = qi;
    g_Qout[i * 128 + tid] = qo;
}

// ---------------- kernel 1c: per-node dst attention term ---------------------
// ndot[v][k] = sum_i node_repr[v][i] * w2a[i][k]  (one warp per node)
__global__ void ndot_kernel(const float* __restrict__ node_repr) {
    int warp = (blockIdx.x * blockDim.x + threadIdx.x) >> 5;
    int lane = threadIdx.x & 31;
    if (warp >= NV) return;
    float4 x = ((const float4*)(node_repr + (size_t)warp * 128))[lane];
    const float4* w2 = ((const float4*)g_w2a) + lane * 4;  // rows i = lane*4 + j
    float s0 = 0.f, s1 = 0.f, s2 = 0.f, s3 = 0.f;
    float4 wv;
    wv = w2[0]; s0 = fmaf(x.x, wv.x, s0); s1 = fmaf(x.x, wv.y, s1); s2 = fmaf(x.x, wv.z, s2); s3 = fmaf(x.x, wv.w, s3);
    wv = w2[1]; s0 = fmaf(x.y, wv.x, s0); s1 = fmaf(x.y, wv.y, s1); s2 = fmaf(x.y, wv.z, s2); s3 = fmaf(x.y, wv.w, s3);
    wv = w2[2]; s0 = fmaf(x.z, wv.x, s0); s1 = fmaf(x.z, wv.y, s1); s2 = fmaf(x.z, wv.z, s2); s3 = fmaf(x.z, wv.w, s3);
    wv = w2[3]; s0 = fmaf(x.w, wv.x, s0); s1 = fmaf(x.w, wv.y, s1); s2 = fmaf(x.w, wv.z, s2); s3 = fmaf(x.w, wv.w, s3);
#pragma unroll
    for (int off = 16; off > 0; off >>= 1) {
        s0 += __shfl_xor_sync(0xFFFFFFFFu, s0, off);
        s1 += __shfl_xor_sync(0xFFFFFFFFu, s1, off);
        s2 += __shfl_xor_sync(0xFFFFFFFFu, s2, off);
        s3 += __shfl_xor_sync(0xFFFFFFFFu, s3, off);
    }
    if (lane == 0)
        ((float4*)g_ndot)[warp] = make_float4(s0, s1, s2, s3);
}

// ---------------- kernel 2: edge kernel (round-12 + red.v4 column perm) ------
// Q columns permuted within each 16-col block at staging so each lane's MMA
// fragments cover 4 CONSECUTIVE real columns -> red.global.add.v4 scatter.
// perm: phys offset o = 8h+2q+b  ->  real offset 4q+2h+b  (bijection).
__global__ void __launch_bounds__(256, 2) edge_kernel(
    const float* __restrict__ node_repr, const float* __restrict__ rel_repr,
    const int* __restrict__ src, const int* __restrict__ dst,
    const int* __restrict__ etype, const float* __restrict__ nrm) {
    extern __shared__ __align__(16) char smem[];
    uint32_t sb = smem_u32(smem);
    float* s_scale = (float*)(smem + SM_SCALE);
    int*   s_dst   = (int*)(smem + SM_DST);

    int tid = threadIdx.x;
    int wid = tid >> 5;
    int lane = tid & 31;
    int cta = blockIdx.x;
    int halfsel = (cta >= GRID_HALF) ? 1 : 0;
    int tile0 = cta - halfsel * GRID_HALF;
    const float* Q = halfsel ? g_Qout : g_Qin;

    // ---- stage Q as bf16 hi/lo, [n_phys][k], with intra-16-block column perm ----
    for (int idx = tid; idx < 16384; idx += 256) {
        int n = idx >> 7, k = idx & 127;
        int o = n & 15;
        int real = (n & ~15) | (((o & 6) << 1) | ((o & 8) >> 2) | (o & 1));
        float v = Q[k * 128 + real];
        __nv_bfloat16 hi = __float2bfloat16(v);
        __nv_bfloat16 lo = __float2bfloat16(v - __bfloat162float(hi));
        *(__nv_bfloat16*)(smem + SM_QHI + n * QSTRB + k * 2) = hi;
        *(__nv_bfloat16*)(smem + SM_QLO + n * QSTRB + k * 2) = lo;
    }

    // gather mapping: 4 threads per edge, interleaved 4-float slices
    int e    = tid >> 2;
    int l4   = tid & 3;

    // warp tiling: 4 row-bands x 2 col-halves (16 edges x 64 cols per warp)
    int rb = wid & 3, ch = wid >> 2;
    int eb = rb * 16;

    // ldmatrix lane addressing
    int arin = lane & 7;
    uint32_t a_row  = (uint32_t)(eb + ((lane >> 3) & 1) * 8 + arin);
    uint32_t a_coff = (uint32_t)((lane >> 4) * 16);
    uint32_t ahi_base = sb + SM_AHI + a_row * QSTRB + a_coff;
    uint32_t alo_base = sb + SM_ALO + a_row * QSTRB + a_coff;
    uint32_t b_row  = (uint32_t)((lane >> 4) * 8 + arin);
    uint32_t b_coff = (uint32_t)(((lane >> 3) & 1) * 16);

    for (int t = tile0; t < HALF_TILES; t += GRID_HALF) {
        __syncthreads();   // prior tile fully consumed (GEMM + scatter done)
        int e0 = (t + halfsel * HALF_TILES) * TILE_E;

        // ---- gather + compose + logits; store comp bf16 hi/lo ----
        {
            int isrc = __ldg(src + e0 + e);
            int idst = __ldg(dst + e0 + e);
            int iet  = __ldg(etype + e0 + e);
            float nv = __ldg(nrm + e0 + e);
            if (l4 == 0) s_dst[e] = idst;

            const float4* xs = (const float4*)(node_repr + (size_t)isrc * 128) + l4;
            const float4* rr = (const float4*)(rel_repr  + (size_t)iet  * 128) + l4;
            const float4* w1 = ((const float4*)g_w1a) + l4 * 4;
            float lg0 = 0.f, lg1 = 0.f, lg2 = 0.f, lg3 = 0.f;
#pragma unroll 4
            for (int q = 0; q < 8; q++) {
                float4 a = xs[q * 4], r4 = rr[q * 4];
                float4 c;
                c.x = a.x * r4.x; c.y = a.y * r4.y; c.z = a.z * r4.z; c.w = a.w * r4.w;
                {
                    __nv_bfloat162 h01 = __floats2bfloat162_rn(c.x, c.y);
                    __nv_bfloat162 h23 = __floats2bfloat162_rn(c.z, c.w);
                    __nv_bfloat162 l01 = __floats2bfloat162_rn(
                        c.x - __bfloat162float(h01.x), c.y - __bfloat162float(h01.y));
                    __nv_bfloat162 l23 = __floats2bfloat162_rn(
                        c.z - __bfloat162float(h23.x), c.w - __bfloat162float(h23.y));
                    uint32_t coff = (uint32_t)(e * QSTRB + (l4 * 4 + q * 16) * 2);
                    uint2 hv, lv;
                    hv.x = *(uint32_t*)&h01; hv.y = *(uint32_t*)&h23;
                    lv.x = *(uint32_t*)&l01; lv.y = *(uint32_t*)&l23;
                    *(uint2*)(smem + SM_AHI + coff) = hv;
                    *(uint2*)(smem + SM_ALO + coff) = lv;
                }
                int ib = q * 16;
                float4 wv;
                wv = w1[ib + 0]; lg0 = fmaf(c.x, wv.x, lg0); lg1 = fmaf(c.x, wv.y, lg1); lg2 = fmaf(c.x, wv.z, lg2); lg3 = fmaf(c.x, wv.w, lg3);
                wv = w1[ib + 1]; lg0 = fmaf(c.y, wv.x, lg0); lg1 = fmaf(c.y, wv.y, lg1); lg2 = fmaf(c.y, wv.z, lg2); lg3 = fmaf(c.y, wv.w, lg3);
                wv = w1[ib + 2]; lg0 = fmaf(c.z, wv.x, lg0); lg1 = fmaf(c.z, wv.y, lg1); lg2 = fmaf(c.z, wv.z, lg2); lg3 = fmaf(c.z, wv.w, lg3);
                wv = w1[ib + 3]; lg0 = fmaf(c.w, wv.x, lg0); lg1 = fmaf(c.w, wv.y, lg1); lg2 = fmaf(c.w, wv.z, lg2); lg3 = fmaf(c.w, wv.w, lg3);
            }
            lg0 += __shfl_xor_sync(0xFFFFFFFFu, lg0, 1);
            lg1 += __shfl_xor_sync(0xFFFFFFFFu, lg1, 1);
            lg2 += __shfl_xor_sync(0xFFFFFFFFu, lg2, 1);
            lg3 += __shfl_xor_sync(0xFFFFFFFFu, lg3, 1);
            lg0 += __shfl_xor_sync(0xFFFFFFFFu, lg0, 2);
            lg1 += __shfl_xor_sync(0xFFFFFFFFu, lg1, 2);
            lg2 += __shfl_xor_sync(0xFFFFFFFFu, lg2, 2);
            lg3 += __shfl_xor_sync(0xFFFFFFFFu, lg3, 2);
            if (l4 == 0) {
                float4 nd = __ldg(((const float4*)g_ndot) + idst);
                float l0 = fmaxf(lg0 + nd.x, 0.f);
                float l1 = fmaxf(lg1 + nd.y, 0.f);
                float l2 = fmaxf(lg2 + nd.z, 0.f);
                float l3 = fmaxf(lg3 + nd.w, 0.f);
                float e0x = expf(l0), e1x = expf(l1), e2x = expf(l2), e3x = expf(l3);
                float inv = nv / (e0x + e1x + e2x + e3x);   // /3 applied in node kernel
                s_scale[e * 4 + 0] = e0x * inv;
                s_scale[e * 4 + 1] = e1x * inv;
                s_scale[e * 4 + 2] = e2x * inv;
                s_scale[e * 4 + 3] = e3x * inv;
            }
        }
        __syncthreads();

        // ---- GEMM: 16 edges x 64 cols per warp, K=128, 3 bf16-split passes ----
        float c[8][4];
#pragma unroll
        for (int nt = 0; nt < 8; nt++)
#pragma unroll
            for (int j = 0; j < 4; j++) c[nt][j] = 0.f;

#pragma unroll 1
        for (int k = 0; k < 8; k++) {
            uint32_t ahi[4], alo[4];
            ldsm_x4(ahi[0], ahi[1], ahi[2], ahi[3], ahi_base + k * 32);
            ldsm_x4(alo[0], alo[1], alo[2], alo[3], alo_base + k * 32);
#pragma unroll
            for (int np = 0; np < 4; np++) {
                int nb = ch * 64 + np * 16;
                uint32_t bh[4], bl[4];
                uint32_t boff = (uint32_t)(nb + b_row) * QSTRB + b_coff + k * 32;
                ldsm_x4(bh[0], bh[1], bh[2], bh[3], sb + SM_QHI + boff);
                ldsm_x4(bl[0], bl[1], bl[2], bl[3], sb + SM_QLO + boff);
                mma_bf16(c[2 * np],     ahi, bh[0], bh[1]);
                mma_bf16(c[2 * np],     ahi, bl[0], bl[1]);
                mma_bf16(c[2 * np],     alo, bh[0], bh[1]);
                mma_bf16(c[2 * np + 1], ahi, bh[2], bh[3]);
                mma_bf16(c[2 * np + 1], ahi, bl[2], bl[3]);
                mma_bf16(c[2 * np + 1], alo, bh[2], bh[3]);
            }
        }

        // ---- scale + scatter: red.v4 on 4 consecutive real cols per quad ----
        // lane quad q: real cols ch*64 + 16*np + 4*q + {0..3}
        //   = {c[2np][0], c[2np][1], c[2np+1][0], c[2np+1][1]} for row er0
        //   = {c[2np][2], c[2np][3], c[2np+1][2], c[2np+1][3]} for row er1
        {
            int er0 = eb + (lane >> 2);
            int er1 = er0 + 8;
            int q4 = (lane & 3) * 4;
            float* hp0 = g_hacc + (size_t)s_dst[er0] * 128;
            float* hp1 = g_hacc + (size_t)s_dst[er1] * 128;
            const float* sp0 = s_scale + er0 * 4;
            const float* sp1 = s_scale + er1 * 4;
#pragma unroll
            for (int np = 0; np < 4; np++) {
                int nbase = ch * 64 + np * 16 + q4;
                int kfac = nbase >> 5;
                float s0 = sp0[kfac], s1 = sp1[kfac];
                asm volatile("red.global.add.v4.f32 [%0], {%1, %2, %3, %4};"
                    :: "l"(hp0 + nbase),
                       "f"(c[2 * np][0] * s0), "f"(c[2 * np][1] * s0),
                       "f"(c[2 * np + 1][0] * s0), "f"(c[2 * np + 1][1] * s0)
                    : "memory");
                asm volatile("red.global.add.v4.f32 [%0], {%1, %2, %3, %4};"
                    :: "l"(hp1 + nbase),
                       "f"(c[2 * np][2] * s1), "f"(c[2 * np][3] * s1),
                       "f"(c[2 * np + 1][2] * s1), "f"(c[2 * np + 1][3] * s1)
                    : "memory");
            }
        }
    }
}

// ---------------- kernel 3: node kernel (self-loop GEMM + fused BN stats) ---
__global__ void __launch_bounds__(128) node_kernel(
    const float* __restrict__ loop_rel, const float* __restrict__ loop_w,
    const float* __restrict__ bias) {
    extern __shared__ float sm[];
    float* Ws     = sm;                 // 16384
    float* t      = Ws + 16384;         // 64*CSTR
    float* sh     = t + 64 * CSTR;      // 64*CSTR
    float* colsum = sh + 64 * CSTR;     // 128
    float* colsq  = colsum + 128;       // 128

    int tid = threadIdx.x;
    int row0 = blockIdx.x * 64;

    {
        const float4* Wg = (const float4*)loop_w;
        float4* Ws4 = (float4*)Ws;
#pragma unroll
        for (int q = 0; q < 32; q++) Ws4[tid + q * 128] = Wg[tid + q * 128];
    }
    if (tid < 128) { colsum[tid] = 0.f; colsq[tid] = 0.f; }

    {
        int e = tid >> 1;
        int ioff = (tid & 1) * 64;
        int row = row0 + e;
        float* tp = t + e * CSTR + ioff;
        float* hp = sh + e * CSTR + ioff;
        if (row < NV) {
            const float4* hv4 = (const float4*)(g_hacc + (size_t)row * 128 + ioff);
            const float4* lr4 = (const float4*)(loop_rel + ioff);
#pragma unroll
            for (int q = 0; q < 16; q++) {
                float4 hh = hv4[q];
                hh.x *= (1.f / 3.f); hh.y *= (1.f / 3.f); hh.z *= (1.f / 3.f); hh.w *= (1.f / 3.f);
                *(float4*)(hp + q * 4) = hh;
                float4 lr = lr4[q];
                float4 tv;
                tv.x = hh.x * lr.x; tv.y = hh.y * lr.y; tv.z = hh.z * lr.z; tv.w = hh.w * lr.w;
                *(float4*)(tp + q * 4) = tv;
            }
        } else {
            float4 z = make_float4(0.f, 0.f, 0.f, 0.f);
#pragma unroll
            for (int q = 0; q < 16; q++) {
                *(float4*)(hp + q * 4) = z;
                *(float4*)(tp + q * 4) = z;
            }
        }
    }
    __syncthreads();

    int c4 = tid & 15, r = tid >> 4;
    float acc[8][8];
#pragma unroll
    for (int u = 0; u < 8; u++)
#pragma unroll
        for (int m = 0; m < 8; m++) acc[u][m] = 0.f;

    const float* ap = t + (r * 8) * CSTR;
    const float* bp = Ws + c4 * 4;
#pragma unroll 1
    for (int k = 0; k < 128; k += 4) {
#pragma unroll
        for (int kk = 0; kk < 4; kk++) {
            const float* brow = bp + (k + kk) * 128;
            float bv[8];
#pragma unroll
            for (int m = 0; m < 4; m++) bv[m] = brow[m];
#pragma unroll
            for (int m = 0; m < 4; m++) bv[4 + m] = brow[64 + m];
#pragma unroll
            for (int u = 0; u < 8; u++) {
                float av = ap[u * CSTR + k + kk];
#pragma unroll
                for (int m = 0; m < 8; m++) acc[u][m] = fmaf(av, bv[m], acc[u][m]);
            }
        }
    }

    float psum[8], psq[8];
#pragma unroll
    for (int m = 0; m < 8; m++) { psum[m] = 0.f; psq[m] = 0.f; }
#pragma unroll
    for (int u = 0; u < 8; u++) {
        int e = r * 8 + u;
        int row = row0 + e;
        if (row < NV) {
#pragma unroll
            for (int m = 0; m < 8; m++) {
                int col = (m < 4) ? (c4 * 4 + m) : (64 + c4 * 4 + m - 4);
                float v = sh[e * CSTR + col] + acc[u][m] * (1.f / 3.f) + bias[col];
                g_h2[(size_t)row * 128 + col] = v;
                psum[m] += v;
                psq[m] = fmaf(v, v, psq[m]);
            }
        }
    }
#pragma unroll
    for (int m = 0; m < 8; m++) {
        int col = (m < 4) ? (c4 * 4 + m) : (64 + c4 * 4 + m - 4);
        atomicAdd(&colsum[col], psum[m]);
        atomicAdd(&colsq[col], psq[m]);
    }
    __syncthreads();
    if (tid < 128) {
        atomicAdd(&g_sum[tid], colsum[tid]);
        atomicAdd(&g_sumsq[tid], colsq[tid]);
    }
}

// ---------------- kernel 4: batchnorm + tanh ---------------------------------
__global__ void finalize_kernel(const float* __restrict__ gamma,
                                const float* __restrict__ beta,
                                float* __restrict__ out) {
    __shared__ float sa[128], sb_[128];
    int tid = threadIdx.x;
    if (tid < 128) {
        float mean = g_sum[tid] * (1.f / NV);
        float var = g_sumsq[tid] * (1.f / NV) - mean * mean;
        float a = gamma[tid] * rsqrtf(var + 1e-5f);
        sa[tid] = a;
        sb_[tid] = beta[tid] - mean * a;
    }
    __syncthreads();
    const int n4 = NV * FOUT / 4;
    for (int i = blockIdx.x * blockDim.x + tid; i < n4; i += gridDim.x * blockDim.x) {
        float4 v = ((const float4*)g_h2)[i];
        int c0 = (i * 4) & 127;
        float4 y;
        y.x = tanhf(fmaf(v.x, sa[c0 + 0], sb_[c0 + 0]));
        y.y = tanhf(fmaf(v.y, sa[c0 + 1], sb_[c0 + 1]));
        y.z = tanhf(fmaf(v.z, sa[c0 + 2], sb_[c0 + 2]));
        y.w = tanhf(fmaf(v.w, sa[c0 + 3], sb_[c0 + 3]));
        ((float4*)out)[i] = y;
    }
}

// ---------------- kernel 5: rel_out = rel_repr @ w_rel -----------------------
__global__ void relout_kernel(const float* __restrict__ rel_repr,
                              const float* __restrict__ w_rel,
                              float* __restrict__ out) {
    __shared__ float rrow[128];
    int b = blockIdx.x, tid = threadIdx.x;
    rrow[tid] = rel_repr[b * 128 + tid];
    __syncthreads();
    float s = 0.f;
#pragma unroll 4
    for (int i = 0; i < 128; i++) s = fmaf(rrow[i], w_rel[i * 128 + tid], s);
    out[(size_t)NV * FOUT + b * 128 + tid] = s;
}

// ---------------- host launcher ----------------------------------------------
extern "C" void kernel_launch(void* const* d_in, const int* in_sizes, int n_in,
                              void* d_out, int out_size) {
    const float* node_repr  = (const float*)d_in[0];
    const float* rel_repr   = (const float*)d_in[1];
    const int*   src        = (const int*)d_in[2];
    const int*   dst        = (const int*)d_in[3];
    const int*   etype      = (const int*)d_in[4];
    const float* nrm        = (const float*)d_in[5];
    const float* node_w     = (const float*)d_in[6];
    const float* node_rel_w = (const float*)d_in[7];
    const float* in_w       = (const float*)d_in[8];
    const float* out_w      = (const float*)d_in[9];
    const float* att_w      = (const float*)d_in[10];
    const float* loop_rel   = (const float*)d_in[11];
    const float* loop_w     = (const float*)d_in[12];
    const float* w_rel      = (const float*)d_in[13];
    const float* bias       = (const float*)d_in[14];
    const float* bn_gamma   = (const float*)d_in[15];
    const float* bn_beta    = (const float*)d_in[16];
    float* out = (float*)d_out;

    static const int NODE_SMEM = (16384 + 2 * 64 * CSTR + 256) * 4;
    cudaFuncSetAttribute(edge_kernel, cudaFuncAttributeMaxDynamicSharedMemorySize, EDGE_SMEM);
    cudaFuncSetAttribute(node_kernel, cudaFuncAttributeMaxDynamicSharedMemorySize, NODE_SMEM);

    zero_kernel<<<512, 256>>>();
    wfold_kernel<<<1, 128>>>(node_w, node_rel_w, att_w);
    qfold_kernel<<<128, 128>>>(node_rel_w, in_w, out_w);
    ndot_kernel<<<(NV + 7) / 8, 256>>>(node_repr);
    edge_kernel<<<2 * GRID_HALF, 256, EDGE_SMEM>>>(node_repr, rel_repr, src, dst, etype, nrm);
    node_kernel<<<(NV + 63) / 64, 128, NODE_SMEM>>>(loop_rel, loop_w, bias);
    finalize_kernel<<<1024, 256>>>(bn_gamma, bn_beta, out);
    relout_kernel<<<R2, 128>>>(rel_repr, w_rel, out);
}